// round 1
// baseline (speedup 1.0000x reference)
#include <cuda_runtime.h>
#include <math.h>

#define NLEV  16
#define NENC  65536
#define NFEAT 32
#define NH    64
#define TPB   128

struct LP { int res[NLEV]; int dense[NLEV]; };

// ---- shared-memory weight layout (float offsets) ----
#define O_DW1 0        // 32*64 = 2048
#define O_DB1 2048     // 64
#define O_DW2 2112     // 64*64 = 4096
#define O_DB2 6208     // 64
#define O_DW3 6272     // 64*16 = 1024
#define O_DB3 7296     // 16
#define O_CW1 7312     // 16*64 = 1024
#define O_CB1 8336     // 64
#define O_CW2 8400     // 4096
#define O_CB2 12496    // 64
#define O_CW3 12560    // 4096
#define O_CB3 16656    // 64
#define O_CW4 16720    // 64*3 = 192
#define O_CB4 16912    // 3
#define SMEM_FLOATS 16915
#define SMEM_BYTES  (SMEM_FLOATS * 4)

// Fully-unrolled dense layer: activations in registers, weights broadcast from smem.
template<int IN, int OUT, bool RELU>
__device__ __forceinline__ void layerf(const float* __restrict__ a, float* __restrict__ o,
                                       const float* __restrict__ w, const float* __restrict__ b)
{
#pragma unroll
    for (int j = 0; j < OUT; j += 4) {
        float4 acc = *(const float4*)(b + j);
#pragma unroll
        for (int i = 0; i < IN; i++) {
            float4 w4 = *(const float4*)(w + i * OUT + j);
            float v = a[i];
            acc.x = fmaf(v, w4.x, acc.x);
            acc.y = fmaf(v, w4.y, acc.y);
            acc.z = fmaf(v, w4.z, acc.z);
            acc.w = fmaf(v, w4.w, acc.w);
        }
        if (RELU) {
            acc.x = fmaxf(acc.x, 0.f); acc.y = fmaxf(acc.y, 0.f);
            acc.z = fmaxf(acc.z, 0.f); acc.w = fmaxf(acc.w, 0.f);
        }
        o[j] = acc.x; o[j + 1] = acc.y; o[j + 2] = acc.z; o[j + 3] = acc.w;
    }
}

__global__ __launch_bounds__(TPB, 2)
void nerf_fused(const float* __restrict__ x, const float2* __restrict__ tables,
                const float* __restrict__ dw1, const float* __restrict__ db1,
                const float* __restrict__ dw2, const float* __restrict__ db2,
                const float* __restrict__ dw3, const float* __restrict__ db3,
                const float* __restrict__ cw1, const float* __restrict__ cb1,
                const float* __restrict__ cw2, const float* __restrict__ cb2,
                const float* __restrict__ cw3, const float* __restrict__ cb3,
                const float* __restrict__ cw4, const float* __restrict__ cb4,
                float* __restrict__ out, LP lp, int npts)
{
    extern __shared__ float sw[];
    {
        int t = threadIdx.x;
        for (int i = t; i < 2048; i += TPB) sw[O_DW1 + i] = dw1[i];
        for (int i = t; i < 64;   i += TPB) sw[O_DB1 + i] = db1[i];
        for (int i = t; i < 4096; i += TPB) sw[O_DW2 + i] = dw2[i];
        for (int i = t; i < 64;   i += TPB) sw[O_DB2 + i] = db2[i];
        for (int i = t; i < 1024; i += TPB) sw[O_DW3 + i] = dw3[i];
        for (int i = t; i < 16;   i += TPB) sw[O_DB3 + i] = db3[i];
        for (int i = t; i < 1024; i += TPB) sw[O_CW1 + i] = cw1[i];
        for (int i = t; i < 64;   i += TPB) sw[O_CB1 + i] = cb1[i];
        for (int i = t; i < 4096; i += TPB) sw[O_CW2 + i] = cw2[i];
        for (int i = t; i < 64;   i += TPB) sw[O_CB2 + i] = cb2[i];
        for (int i = t; i < 4096; i += TPB) sw[O_CW3 + i] = cw3[i];
        for (int i = t; i < 64;   i += TPB) sw[O_CB3 + i] = cb3[i];
        for (int i = t; i < 192;  i += TPB) sw[O_CW4 + i] = cw4[i];
        for (int i = t; i < 3;    i += TPB) sw[O_CB4 + i] = cb4[i];
    }
    __syncthreads();

    int pt = blockIdx.x * TPB + threadIdx.x;
    if (pt >= npts) return;

    float px = x[3 * pt + 0], py = x[3 * pt + 1], pz = x[3 * pt + 2];

    // ---- hash-grid encode: 16 levels x trilinear 8-corner gather ----
    float h[NFEAT];
#pragma unroll
    for (int l = 0; l < NLEV; l++) {
        int res = lp.res[l];
        float s = (float)(res - 1);
        float qx = fmaf(px, 0.5f, 0.5f) * s;
        float qy = fmaf(py, 0.5f, 0.5f) * s;
        float qz = fmaf(pz, 0.5f, 0.5f) * s;
        int cx = min(max((int)floorf(qx), 0), res - 2);
        int cy = min(max((int)floorf(qy), 0), res - 2);
        int cz = min(max((int)floorf(qz), 0), res - 2);
        float wx = qx - (float)cx, wy = qy - (float)cy, wz = qz - (float)cz;
        const float2* tab = tables + (size_t)l * NENC;
        int dense = lp.dense[l];
        float f0 = 0.f, f1 = 0.f;
#pragma unroll
        for (int n = 0; n < 8; n++) {
            int dx = (n >> 2) & 1, dy = (n >> 1) & 1, dz = n & 1;
            unsigned gx = (unsigned)(cx + dx);
            unsigned gy = (unsigned)(cy + dy);
            unsigned gz = (unsigned)(cz + dz);
            unsigned idx;
            if (dense)
                idx = gx + (unsigned)res * (gy + (unsigned)res * gz);
            else
                idx = (gx * 1u ^ gy * 2654435761u ^ gz * 805459861u) & 65535u;
            float2 e = __ldg(tab + idx);
            float wc = (dx ? wx : 1.f - wx) * (dy ? wy : 1.f - wy) * (dz ? wz : 1.f - wz);
            f0 = fmaf(wc, e.x, f0);
            f1 = fmaf(wc, e.y, f1);
        }
        h[2 * l] = f0; h[2 * l + 1] = f1;
    }

    // ---- MLP ----
    float d1[NH]; layerf<NFEAT, NH, true >(h,  d1, sw + O_DW1, sw + O_DB1);
    float d2[NH]; layerf<NH,    NH, true >(d1, d2, sw + O_DW2, sw + O_DB2);
    float dd[16]; layerf<NH,    16, false>(d2, dd, sw + O_DW3, sw + O_DB3);
    float sigma = expf(dd[0]);
    float c1[NH]; layerf<16, NH, true>(dd, c1, sw + O_CW1, sw + O_CB1);
    float c2[NH]; layerf<NH, NH, true>(c1, c2, sw + O_CW2, sw + O_CB2);
    float c3[NH]; layerf<NH, NH, true>(c2, c3, sw + O_CW3, sw + O_CB3);

    float cc[3];
#pragma unroll
    for (int j = 0; j < 3; j++) {
        float acc = sw[O_CB4 + j];
#pragma unroll
        for (int i = 0; i < NH; i++)
            acc = fmaf(c3[i], sw[O_CW4 + i * 3 + j], acc);
        cc[j] = 1.f / (1.f + expf(-acc));
    }

    // output: [sigma (B)] then [c (B,3) row-major]
    out[pt] = sigma;
    out[npts + 3 * pt + 0] = cc[0];
    out[npts + 3 * pt + 1] = cc[1];
    out[npts + 3 * pt + 2] = cc[2];
}

extern "C" void kernel_launch(void* const* d_in, const int* in_sizes, int n_in,
                              void* d_out, int out_size)
{
    const float*  x      = (const float*) d_in[0];
    const float2* tables = (const float2*)d_in[1];
    const float*  dw1 = (const float*)d_in[2];
    const float*  db1 = (const float*)d_in[3];
    const float*  dw2 = (const float*)d_in[4];
    const float*  db2 = (const float*)d_in[5];
    const float*  dw3 = (const float*)d_in[6];
    const float*  db3 = (const float*)d_in[7];
    const float*  cw1 = (const float*)d_in[8];
    const float*  cb1 = (const float*)d_in[9];
    const float*  cw2 = (const float*)d_in[10];
    const float*  cb2 = (const float*)d_in[11];
    const float*  cw3 = (const float*)d_in[12];
    const float*  cb3 = (const float*)d_in[13];
    const float*  cw4 = (const float*)d_in[14];
    const float*  cb4 = (const float*)d_in[15];
    float* out = (float*)d_out;

    int npts = in_sizes[0] / 3;

    // Replicate numpy's float64 resolution schedule exactly.
    LP lp;
    double growth = exp((log(512.0) - log(16.0)) / 15.0);
    for (int l = 0; l < NLEV; l++) {
        int r = (int)floor(16.0 * pow(growth, (double)l));
        lp.res[l]   = r;
        lp.dense[l] = ((long long)r * r * r <= 65536LL) ? 1 : 0;
    }

    cudaFuncSetAttribute(nerf_fused, cudaFuncAttributeMaxDynamicSharedMemorySize, SMEM_BYTES);
    int grid = (npts + TPB - 1) / TPB;
    nerf_fused<<<grid, TPB, SMEM_BYTES>>>(x, tables, dw1, db1, dw2, db2, dw3, db3,
                                          cw1, cb1, cw2, cb2, cw3, cb3, cw4, cb4,
                                          out, lp, npts);
}

// round 14
// speedup vs baseline: 1.7790x; 1.7790x over previous
#include <cuda_runtime.h>
#include <math.h>
#include <stdint.h>

#define NLEV 16
#define NENC 65536
#define TPB  128
#define AST  68   // activation/weight row stride in floats (bank-conflict-free)

struct LP { int res[NLEV]; int dense[NLEV]; };

// ---- smem layout (float offsets) ----
#define W_DW1 0                    // 32x68
#define W_DW2 (W_DW1 + 32*68)      // 64x68
#define W_DW3 (W_DW2 + 64*68)      // 64x20 (N=16 padded to 20)
#define W_CW1 (W_DW3 + 64*20)      // 16x68
#define W_CW2 (W_CW1 + 16*68)      // 64x68
#define W_CW3 (W_CW2 + 64*68)      // 64x68
#define W_CW4 (W_CW3 + 64*68)      // 64x3 raw fp32
#define B_DB1 (W_CW4 + 192)
#define B_DB2 (B_DB1 + 64)
#define B_DB3 (B_DB2 + 64)
#define B_CB1 (B_DB3 + 16)
#define B_CB2 (B_CB1 + 64)
#define B_CB3 (B_CB2 + 64)
#define B_CB4 (B_CB3 + 64)
#define O_ACT (B_CB4 + 4)
#define ACT_PER_WARP (32*AST)
#define O_SRAW (O_ACT + 4*ACT_PER_WARP)   // 32 raw fp32 dd0 per warp
#define SMEM_FLOATS (O_SRAW + 128)
#define SMEM_BYTES  (SMEM_FLOATS * 4)

__device__ __forceinline__ float to_tf32(float f) {
    float r;
    asm("cvt.rna.tf32.f32 %0, %1;" : "=f"(r) : "f"(f));
    return r;
}

__device__ __forceinline__ void mma_tf32(float* c, const uint32_t* a, const uint32_t* b) {
    asm volatile(
        "mma.sync.aligned.m16n8k8.row.col.f32.tf32.tf32.f32 "
        "{%0,%1,%2,%3}, {%4,%5,%6,%7}, {%8,%9}, {%0,%1,%2,%3};"
        : "+f"(c[0]), "+f"(c[1]), "+f"(c[2]), "+f"(c[3])
        : "r"(a[0]), "r"(a[1]), "r"(a[2]), "r"(a[3]), "r"(b[0]), "r"(b[1]));
}

// One dense layer on tensor cores. Warp computes its 32 rows x N cols.
// A: act buffer (32 rows, stride AST, tf32 values). W: KxN padded to WS. In-place output.
template<int K, int N, int WS, bool RELU, bool SAVE0>
__device__ __forceinline__ void mma_layer(float* __restrict__ act,
                                          const float* __restrict__ w,
                                          const float* __restrict__ bias,
                                          float* __restrict__ sraw)
{
    const int lane = threadIdx.x & 31;
    const int g = lane >> 2, tg = lane & 3;

    float acc[2][N / 8][4];
#pragma unroll
    for (int mt = 0; mt < 2; mt++)
#pragma unroll
        for (int nt = 0; nt < N / 8; nt++) {
            float b0 = bias[nt * 8 + 2 * tg], b1 = bias[nt * 8 + 2 * tg + 1];
            acc[mt][nt][0] = b0; acc[mt][nt][1] = b1;
            acc[mt][nt][2] = b0; acc[mt][nt][3] = b1;
        }

#pragma unroll
    for (int ks = 0; ks < K / 8; ks++) {
        uint32_t a[2][4];
#pragma unroll
        for (int mt = 0; mt < 2; mt++) {
            const float* ap = act + (mt * 16 + g) * AST + ks * 8 + tg;
            a[mt][0] = __float_as_uint(ap[0]);
            a[mt][1] = __float_as_uint(ap[8 * AST]);
            a[mt][2] = __float_as_uint(ap[4]);
            a[mt][3] = __float_as_uint(ap[8 * AST + 4]);
        }
#pragma unroll
        for (int nt = 0; nt < N / 8; nt++) {
            uint32_t b[2];
            const float* bp = w + (ks * 8 + tg) * WS + nt * 8 + g;
            b[0] = __float_as_uint(bp[0]);
            b[1] = __float_as_uint(bp[4 * WS]);
#pragma unroll
            for (int mt = 0; mt < 2; mt++) mma_tf32(acc[mt][nt], a[mt], b);
        }
    }

    __syncwarp();   // all A reads done before in-place overwrite
#pragma unroll
    for (int mt = 0; mt < 2; mt++)
#pragma unroll
        for (int nt = 0; nt < N / 8; nt++) {
            float* c = acc[mt][nt];
            if (SAVE0 && nt == 0 && tg == 0) {   // raw fp32 dd[:,0] for sigma
                sraw[mt * 16 + g]     = c[0];
                sraw[mt * 16 + g + 8] = c[2];
            }
            if (RELU) {
                c[0] = fmaxf(c[0], 0.f); c[1] = fmaxf(c[1], 0.f);
                c[2] = fmaxf(c[2], 0.f); c[3] = fmaxf(c[3], 0.f);
            }
            float* op = act + (mt * 16 + g) * AST + nt * 8 + 2 * tg;
            op[0]           = to_tf32(c[0]); op[1]           = to_tf32(c[1]);
            op[8 * AST]     = to_tf32(c[2]); op[8 * AST + 1] = to_tf32(c[3]);
        }
    __syncwarp();
}

__global__ __launch_bounds__(TPB, 2)
void nerf_fused(const float* __restrict__ x, const float2* __restrict__ tables,
                const float* __restrict__ dw1, const float* __restrict__ db1,
                const float* __restrict__ dw2, const float* __restrict__ db2,
                const float* __restrict__ dw3, const float* __restrict__ db3,
                const float* __restrict__ cw1, const float* __restrict__ cb1,
                const float* __restrict__ cw2, const float* __restrict__ cb2,
                const float* __restrict__ cw3, const float* __restrict__ cb3,
                const float* __restrict__ cw4, const float* __restrict__ cb4,
                float* __restrict__ out, LP lp, int npts)
{
    extern __shared__ float sw[];
    const int tid = threadIdx.x;

    // ---- stage weights (tf32-converted, padded) + biases ----
    for (int i = tid; i < 32 * 64; i += TPB) sw[W_DW1 + (i >> 6) * AST + (i & 63)] = to_tf32(dw1[i]);
    for (int i = tid; i < 64 * 64; i += TPB) sw[W_DW2 + (i >> 6) * AST + (i & 63)] = to_tf32(dw2[i]);
    for (int i = tid; i < 64 * 16; i += TPB) sw[W_DW3 + (i >> 4) * 20  + (i & 15)] = to_tf32(dw3[i]);
    for (int i = tid; i < 16 * 64; i += TPB) sw[W_CW1 + (i >> 6) * AST + (i & 63)] = to_tf32(cw1[i]);
    for (int i = tid; i < 64 * 64; i += TPB) sw[W_CW2 + (i >> 6) * AST + (i & 63)] = to_tf32(cw2[i]);
    for (int i = tid; i < 64 * 64; i += TPB) sw[W_CW3 + (i >> 6) * AST + (i & 63)] = to_tf32(cw3[i]);
    for (int i = tid; i < 192; i += TPB) sw[W_CW4 + i] = cw4[i];
    for (int i = tid; i < 64;  i += TPB) { sw[B_DB1 + i] = db1[i]; sw[B_DB2 + i] = db2[i];
                                           sw[B_CB1 + i] = cb1[i]; sw[B_CB2 + i] = cb2[i];
                                           sw[B_CB3 + i] = cb3[i]; }
    for (int i = tid; i < 16;  i += TPB) sw[B_DB3 + i] = db3[i];
    for (int i = tid; i < 3;   i += TPB) sw[B_CB4 + i] = cb4[i];
    __syncthreads();

    const int warp = tid >> 5, lane = tid & 31;
    float* act  = sw + O_ACT + warp * ACT_PER_WARP;
    float* sraw = sw + O_SRAW + warp * 32;

    const int pt  = blockIdx.x * TPB + tid;
    const int ptc = min(pt, npts - 1);

    float px = x[3 * ptc + 0], py = x[3 * ptc + 1], pz = x[3 * ptc + 2];

    // ---- hash-grid encode ----
    float h[32];
#pragma unroll
    for (int l = 0; l < NLEV; l++) {
        int res = lp.res[l];
        float s = (float)(res - 1);
        float qx = fmaf(px, 0.5f, 0.5f) * s;
        float qy = fmaf(py, 0.5f, 0.5f) * s;
        float qz = fmaf(pz, 0.5f, 0.5f) * s;
        int cx = min(max((int)floorf(qx), 0), res - 2);
        int cy = min(max((int)floorf(qy), 0), res - 2);
        int cz = min(max((int)floorf(qz), 0), res - 2);
        float wx = qx - (float)cx, wy = qy - (float)cy, wz = qz - (float)cz;
        const float2* tab = tables + (size_t)l * NENC;
        int dense = lp.dense[l];
        float f0 = 0.f, f1 = 0.f;
#pragma unroll
        for (int n = 0; n < 8; n++) {
            int dx = (n >> 2) & 1, dy = (n >> 1) & 1, dz = n & 1;
            unsigned gx = (unsigned)(cx + dx), gy = (unsigned)(cy + dy), gz = (unsigned)(cz + dz);
            unsigned idx;
            if (dense) idx = gx + (unsigned)res * (gy + (unsigned)res * gz);
            else       idx = (gx * 1u ^ gy * 2654435761u ^ gz * 805459861u) & 65535u;
            float2 e = __ldg(tab + idx);
            float wc = (dx ? wx : 1.f - wx) * (dy ? wy : 1.f - wy) * (dz ? wz : 1.f - wz);
            f0 = fmaf(wc, e.x, f0);
            f1 = fmaf(wc, e.y, f1);
        }
        h[2 * l] = f0; h[2 * l + 1] = f1;
    }

    // write features (tf32) into this warp's A buffer, row = lane
    {
        float* row = act + lane * AST;
#pragma unroll
        for (int i = 0; i < 32; i += 4) {
            float4 v = make_float4(to_tf32(h[i]), to_tf32(h[i + 1]),
                                   to_tf32(h[i + 2]), to_tf32(h[i + 3]));
            *(float4*)(row + i) = v;
        }
    }
    __syncwarp();

    // ---- MLP on tensor cores (per-warp, in-place act buffer) ----
    mma_layer<32, 64, AST, true,  false>(act, sw + W_DW1, sw + B_DB1, sraw);
    mma_layer<64, 64, AST, true,  false>(act, sw + W_DW2, sw + B_DB2, sraw);
    mma_layer<64, 16, 20,  false, true >(act, sw + W_DW3, sw + B_DB3, sraw);  // dd, save raw col0
    mma_layer<16, 64, AST, true,  false>(act, sw + W_CW1, sw + B_CB1, sraw);
    mma_layer<64, 64, AST, true,  false>(act, sw + W_CW2, sw + B_CB2, sraw);
    mma_layer<64, 64, AST, true,  false>(act, sw + W_CW3, sw + B_CB3, sraw);

    // ---- final 64->3 + sigmoid, sigma = exp(dd0) ----
    float sigma = expf(sraw[lane]);
    const float* arow = act + lane * AST;
    float a0 = sw[B_CB4 + 0], a1 = sw[B_CB4 + 1], a2 = sw[B_CB4 + 2];
#pragma unroll
    for (int i = 0; i < 64; i++) {
        float v = arow[i];
        a0 = fmaf(v, sw[W_CW4 + 3 * i + 0], a0);
        a1 = fmaf(v, sw[W_CW4 + 3 * i + 1], a1);
        a2 = fmaf(v, sw[W_CW4 + 3 * i + 2], a2);
    }
    if (pt < npts) {
        out[pt] = sigma;
        out[npts + 3 * pt + 0] = 1.f / (1.f + expf(-a0));
        out[npts + 3 * pt + 1] = 1.f / (1.f + expf(-a1));
        out[npts + 3 * pt + 2] = 1.f / (1.f + expf(-a2));
    }
}

extern "C" void kernel_launch(void* const* d_in, const int* in_sizes, int n_in,
                              void* d_out, int out_size)
{
    const float*  x      = (const float*) d_in[0];
    const float2* tables = (const float2*)d_in[1];
    const float* dw1 = (const float*)d_in[2];
    const float* db1 = (const float*)d_in[3];
    const float* dw2 = (const float*)d_in[4];
    const float* db2 = (const float*)d_in[5];
    const float* dw3 = (const float*)d_in[6];
    const float* db3 = (const float*)d_in[7];
    const float* cw1 = (const float*)d_in[8];
    const float* cb1 = (const float*)d_in[9];
    const float* cw2 = (const float*)d_in[10];
    const float* cb2 = (const float*)d_in[11];
    const float* cw3 = (const float*)d_in[12];
    const float* cb3 = (const float*)d_in[13];
    const float* cw4 = (const float*)d_in[14];
    const float* cb4 = (const float*)d_in[15];
    float* out = (float*)d_out;

    int npts = in_sizes[0] / 3;

    LP lp;
    double growth = exp((log(512.0) - log(16.0)) / 15.0);
    for (int l = 0; l < NLEV; l++) {
        int r = (int)floor(16.0 * pow(growth, (double)l));
        lp.res[l] = r;
        lp.dense[l] = ((long long)r * r * r <= 65536LL) ? 1 : 0;
    }

    cudaFuncSetAttribute(nerf_fused, cudaFuncAttributeMaxDynamicSharedMemorySize, SMEM_BYTES);
    int grid = (npts + TPB - 1) / TPB;
    nerf_fused<<<grid, TPB, SMEM_BYTES>>>(x, tables, dw1, db1, dw2, db2, dw3, db3,
                                          cw1, cb1, cw2, cb2, cw3, cb3, cw4, cb4,
                                          out, lp, npts);
}